// round 1
// baseline (speedup 1.0000x reference)
#include <cuda_runtime.h>
#include <math.h>

#define MT 16384   // B*T rows
#define DD 768     // embed dim
#define TQ 32      // query tile
#define JW 288     // key window tile (256 + TQ)

// 1/sqrt(768*256) = 1/(256*sqrt(3))
#define INV_SCALE 0.0022552744890219756f

// scratch (device globals: allocation-free rule)
__device__ float g_H[MT * DD];
__device__ float g_Q[MT * DD];
__device__ float g_K[MT * DD];
__device__ float g_V[MT * DD];

__device__ __forceinline__ float gelu_exact(float x) {
    return 0.5f * x * (1.0f + erff(x * 0.70710678118654752f));
}

// ---------------------------------------------------------------------------
// C[M,768] = epilogue(A[M,768] @ B[768,768] + bias)
// 128x128 tile, BK=8, 256 threads, 8x8 micro-tile. Grid: (6, M/128)
// ---------------------------------------------------------------------------
template<bool GELU>
__global__ void __launch_bounds__(256, 2) gemm_bias_kernel(
    const float* __restrict__ A, const float* __restrict__ B,
    const float* __restrict__ bias, float* __restrict__ C)
{
    __shared__ float As[8][128];
    __shared__ float Bs[8][128];

    const int t  = threadIdx.x;
    const int m0 = blockIdx.y * 128;
    const int n0 = blockIdx.x * 128;
    const int ty = t >> 4;          // 0..15
    const int tx = t & 15;          // 0..15

    const int ar = t >> 1;          // 0..127
    const int ac = (t & 1) * 4;     // 0 or 4
    const int br = t >> 5;          // 0..7
    const int bc = (t & 31) * 4;    // 0..124

    const float* Ap = A + (size_t)(m0 + ar) * DD + ac;
    const float* Bp = B + (size_t)br * DD + n0 + bc;

    float acc[8][8];
    #pragma unroll
    for (int i = 0; i < 8; i++)
        #pragma unroll
        for (int j = 0; j < 8; j++) acc[i][j] = 0.f;

    for (int k0 = 0; k0 < DD; k0 += 8) {
        float4 a4 = *(const float4*)(Ap + k0);
        float4 b4 = *(const float4*)(Bp + (size_t)k0 * DD);
        As[ac + 0][ar] = a4.x; As[ac + 1][ar] = a4.y;
        As[ac + 2][ar] = a4.z; As[ac + 3][ar] = a4.w;
        *(float4*)&Bs[br][bc] = b4;
        __syncthreads();
        #pragma unroll
        for (int kk = 0; kk < 8; kk++) {
            float av[8], bv[8];
            *(float4*)&av[0] = *(float4*)&As[kk][ty * 8];
            *(float4*)&av[4] = *(float4*)&As[kk][ty * 8 + 4];
            *(float4*)&bv[0] = *(float4*)&Bs[kk][tx * 8];
            *(float4*)&bv[4] = *(float4*)&Bs[kk][tx * 8 + 4];
            #pragma unroll
            for (int i = 0; i < 8; i++)
                #pragma unroll
                for (int j = 0; j < 8; j++)
                    acc[i][j] = fmaf(av[i], bv[j], acc[i][j]);
        }
        __syncthreads();
    }

    #pragma unroll
    for (int i = 0; i < 8; i++) {
        const int row = m0 + ty * 8 + i;
        #pragma unroll
        for (int j = 0; j < 8; j++) {
            const int col = n0 + tx * 8 + j;
            float v = acc[i][j] + bias[col];
            if (GELU) v = gelu_exact(v);
            C[(size_t)row * DD + col] = v;
        }
    }
}

// ---------------------------------------------------------------------------
// Fused banded attention + LayerNorm.
// One block = one (batch, 32-query) tile. 256 threads.
// Phase 1: S[32][288] = masked (Q_tile @ K_band^T) / SCALE   (in smem)
// Phase 2: Y[32][768] = S @ V_band                            (in smem)
// Phase 3: row LayerNorm -> out
// ---------------------------------------------------------------------------
__global__ void __launch_bounds__(256) attn_ln_kernel(
    const float* __restrict__ Q, const float* __restrict__ K,
    const float* __restrict__ V, const float* __restrict__ lnw,
    const float* __restrict__ lnb, float* __restrict__ out)
{
    extern __shared__ float sm[];
    float* Ssh = sm;                       // 32*288 = 9216
    float* Ysh = sm + TQ * JW;             // 32*768 = 24576
    float* Wk  = Ysh + TQ * DD;            // 5120 floats workspace
    float* Qs  = Wk;                       // 16*32
    float* Ks  = Wk + 16 * TQ;             // 16*288
    float* Vs  = Wk;                       // 32*128 (reuses workspace)

    const int t  = threadIdx.x;
    const int bx = blockIdx.x;
    const int b  = bx >> 7;                // 128 tiles per batch
    const int it = bx & 127;
    const int i0 = it * TQ;                // batch-local first query row
    const long base = (long)b * 4096;      // global row base of this batch
    const int jb = i0 - 256;               // batch-local window start

    // ---------------- phase 1: scores ----------------
    {
        const int tx = t & 31;             // jw lane
        const int ty = t >> 5;             // ti group (0..7)
        const int lr = t >> 3;             // load row 0..31
        const int lc = (t & 7) * 2;        // load k-offset 0..14

        float acc[4][9];
        #pragma unroll
        for (int i = 0; i < 4; i++)
            #pragma unroll
            for (int j = 0; j < 9; j++) acc[i][j] = 0.f;

        for (int k0 = 0; k0 < DD; k0 += 16) {
            float2 q2 = *(const float2*)&Q[(base + i0 + lr) * DD + k0 + lc];
            Qs[(lc    ) * TQ + lr] = q2.x;
            Qs[(lc + 1) * TQ + lr] = q2.y;
            #pragma unroll
            for (int p = 0; p < 9; p++) {
                const int row = lr + p * 32;
                const int jl  = jb + row;
                float2 kv = make_float2(0.f, 0.f);
                if (jl >= 0)
                    kv = *(const float2*)&K[(base + jl) * DD + k0 + lc];
                Ks[(lc    ) * JW + row] = kv.x;
                Ks[(lc + 1) * JW + row] = kv.y;
            }
            __syncthreads();
            #pragma unroll
            for (int kk = 0; kk < 16; kk++) {
                float qv[4], kv[9];
                #pragma unroll
                for (int i = 0; i < 4; i++) qv[i] = Qs[kk * TQ + ty + 8 * i];
                #pragma unroll
                for (int j = 0; j < 9; j++) kv[j] = Ks[kk * JW + tx + 32 * j];
                #pragma unroll
                for (int i = 0; i < 4; i++)
                    #pragma unroll
                    for (int j = 0; j < 9; j++)
                        acc[i][j] = fmaf(qv[i], kv[j], acc[i][j]);
            }
            __syncthreads();
        }

        // mask + scale + stage scores
        #pragma unroll
        for (int i = 0; i < 4; i++) {
            const int ti = ty + 8 * i;
            #pragma unroll
            for (int j = 0; j < 9; j++) {
                const int jw = tx + 32 * j;
                const int jl = jb + jw;
                // valid: j >= 0 and 0 <= (i - j) < 256  <=>  ti < jw <= ti+256
                const bool valid = (jl >= 0) && (jw > ti) && (jw <= ti + 256);
                Ssh[ti * JW + jw] = valid ? acc[i][j] * INV_SCALE : 0.f;
            }
        }
        __syncthreads();
    }

    // ---------------- phase 2: y = S @ V ----------------
    {
        const int tg = t & 31;             // d group: 4 floats
        const int th = t >> 5;             // ti base (ti = th + 8*ii)
        for (int dc = 0; dc < DD; dc += 128) {
            float acc2[4][4];
            #pragma unroll
            for (int ii = 0; ii < 4; ii++)
                #pragma unroll
                for (int c = 0; c < 4; c++) acc2[ii][c] = 0.f;

            for (int js = 0; js < JW; js += 32) {
                #pragma unroll
                for (int p = 0; p < 4; p++) {
                    const int row = th + p * 8;
                    const int jl  = jb + js + row;
                    float4 vv = make_float4(0.f, 0.f, 0.f, 0.f);
                    if (jl >= 0)
                        vv = *(const float4*)&V[(base + jl) * DD + dc + tg * 4];
                    *(float4*)&Vs[row * 128 + tg * 4] = vv;
                }
                __syncthreads();
                #pragma unroll
                for (int jw = 0; jw < 32; jw++) {
                    const float4 v4 = *(float4*)&Vs[jw * 128 + tg * 4];
                    #pragma unroll
                    for (int ii = 0; ii < 4; ii++) {
                        const float s = Ssh[(th + 8 * ii) * JW + js + jw];
                        acc2[ii][0] = fmaf(s, v4.x, acc2[ii][0]);
                        acc2[ii][1] = fmaf(s, v4.y, acc2[ii][1]);
                        acc2[ii][2] = fmaf(s, v4.z, acc2[ii][2]);
                        acc2[ii][3] = fmaf(s, v4.w, acc2[ii][3]);
                    }
                }
                __syncthreads();
            }
            #pragma unroll
            for (int ii = 0; ii < 4; ii++) {
                const int ti = th + 8 * ii;
                float4 r = make_float4(acc2[ii][0], acc2[ii][1], acc2[ii][2], acc2[ii][3]);
                *(float4*)&Ysh[ti * DD + dc + tg * 4] = r;
            }
        }
        __syncthreads();
    }

    // ---------------- phase 3: LayerNorm ----------------
    {
        const int warp = t >> 5;
        const int lane = t & 31;
        #pragma unroll
        for (int rr = 0; rr < 4; rr++) {
            const int row = warp * 4 + rr;
            float s = 0.f, ss = 0.f;
            #pragma unroll
            for (int c0 = 0; c0 < DD; c0 += 32) {
                const float y = Ysh[row * DD + c0 + lane];
                s += y; ss += y * y;
            }
            #pragma unroll
            for (int o = 16; o > 0; o >>= 1) {
                s  += __shfl_xor_sync(0xffffffffu, s,  o);
                ss += __shfl_xor_sync(0xffffffffu, ss, o);
            }
            const float mu   = s * (1.f / 768.f);
            const float var  = ss * (1.f / 768.f) - mu * mu;
            const float rstd = rsqrtf(var + 1e-5f);
            #pragma unroll
            for (int c0 = 0; c0 < DD; c0 += 32) {
                const int c = c0 + lane;
                const float y = Ysh[row * DD + c];
                out[(base + i0 + row) * DD + c] = (y - mu) * rstd * lnw[c] + lnb[c];
            }
        }
    }
}

// ---------------------------------------------------------------------------
extern "C" void kernel_launch(void* const* d_in, const int* in_sizes, int n_in,
                              void* d_out, int out_size)
{
    const float* x   = (const float*)d_in[0];
    const float* qw1 = (const float*)d_in[1];
    const float* qb1 = (const float*)d_in[2];
    const float* qw2 = (const float*)d_in[3];
    const float* qb2 = (const float*)d_in[4];
    const float* kw1 = (const float*)d_in[5];
    const float* kb1 = (const float*)d_in[6];
    const float* kw2 = (const float*)d_in[7];
    const float* kb2 = (const float*)d_in[8];
    const float* vw1 = (const float*)d_in[9];
    const float* vb1 = (const float*)d_in[10];
    const float* vw2 = (const float*)d_in[11];
    const float* vb2 = (const float*)d_in[12];
    const float* lnw = (const float*)d_in[13];
    const float* lnb = (const float*)d_in[14];
    float* out = (float*)d_out;

    float *H, *Q, *K, *V;
    cudaGetSymbolAddress((void**)&H, g_H);
    cudaGetSymbolAddress((void**)&Q, g_Q);
    cudaGetSymbolAddress((void**)&K, g_K);
    cudaGetSymbolAddress((void**)&V, g_V);

    const dim3 gg(DD / 128, MT / 128);   // (6, 128)

    gemm_bias_kernel<true ><<<gg, 256>>>(x, qw1, qb1, H);
    gemm_bias_kernel<false><<<gg, 256>>>(H, qw2, qb2, Q);
    gemm_bias_kernel<true ><<<gg, 256>>>(x, kw1, kb1, H);
    gemm_bias_kernel<false><<<gg, 256>>>(H, kw2, kb2, K);
    gemm_bias_kernel<true ><<<gg, 256>>>(x, vw1, vb1, H);
    gemm_bias_kernel<false><<<gg, 256>>>(H, vw2, vb2, V);

    const int smem = (TQ * JW + TQ * DD + 5120) * 4;   // 155648 B
    cudaFuncSetAttribute(attn_ln_kernel,
                         cudaFuncAttributeMaxDynamicSharedMemorySize, smem);
    attn_ln_kernel<<<MT / TQ, 256, smem>>>(Q, K, V, lnw, lnb, out);
}

// round 3
// speedup vs baseline: 1.9552x; 1.9552x over previous
#include <cuda_runtime.h>
#include <cuda_bf16.h>
#include <math.h>
#include <stdint.h>

#define MT 16384   // B*T rows
#define DD 768     // embed dim
#define TQ 32      // query tile (attention)
#define JW 288     // key window tile (256 + TQ)

#define BK 32              // k elems per smem chunk
#define NC (DD / BK)       // 24 chunks
#define PADK 40            // padded row length (bf16 elems) -> conflict-free ldmatrix
#define TILE_SM (128 * PADK * 2)        // 10240 B per tile
#define STAGE_SM (4 * TILE_SM)          // Ah, Al, Bh, Bl

// 1/sqrt(768*256) = 1/(256*sqrt(3))
#define INV_SCALE 0.0022552744890219756f

// ---------------------------------------------------------------------------
// scratch (device globals: allocation-free rule)
// ---------------------------------------------------------------------------
__device__ __nv_bfloat16 g_Xh[MT * DD];
__device__ __nv_bfloat16 g_Xl[MT * DD];
__device__ __nv_bfloat16 g_Hh[MT * DD];
__device__ __nv_bfloat16 g_Hl[MT * DD];
__device__ __nv_bfloat16 g_Wth[DD * DD];
__device__ __nv_bfloat16 g_Wtl[DD * DD];
__device__ float g_Q[MT * DD];
__device__ float g_K[MT * DD];
__device__ float g_V[MT * DD];

__device__ __forceinline__ float gelu_exact(float x) {
    return 0.5f * x * (1.0f + erff(x * 0.70710678118654752f));
}

__device__ __forceinline__ uint32_t s2u(const void* p) {
    uint32_t a;
    asm("{ .reg .u64 t; cvta.to.shared.u64 t, %1; cvt.u32.u64 %0, t; }"
        : "=r"(a) : "l"(p));
    return a;
}

// ---- portable tensor-core primitives (compute_80 features) ----------------
__device__ __forceinline__ void mma_bf16(float* c, const uint32_t* a, const uint32_t* b) {
    asm volatile(
        "mma.sync.aligned.m16n8k16.row.col.f32.bf16.bf16.f32 "
        "{%0,%1,%2,%3}, {%4,%5,%6,%7}, {%8,%9}, {%0,%1,%2,%3};"
        : "+f"(c[0]), "+f"(c[1]), "+f"(c[2]), "+f"(c[3])
        : "r"(a[0]), "r"(a[1]), "r"(a[2]), "r"(a[3]), "r"(b[0]), "r"(b[1]));
}

__device__ __forceinline__ void ldsm_x4(uint32_t* r, uint32_t addr) {
    asm volatile("ldmatrix.sync.aligned.m8n8.x4.shared.b16 {%0,%1,%2,%3}, [%4];"
                 : "=r"(r[0]), "=r"(r[1]), "=r"(r[2]), "=r"(r[3]) : "r"(addr));
}

__device__ __forceinline__ void cp_async16(uint32_t dst, const void* src) {
    asm volatile("cp.async.cg.shared.global [%0], [%1], 16;" :: "r"(dst), "l"(src));
}
#define CP_COMMIT()  asm volatile("cp.async.commit_group;" ::: "memory")
#define CP_WAIT_1()  asm volatile("cp.async.wait_group 1;" ::: "memory")
#define CP_WAIT_0()  asm volatile("cp.async.wait_group 0;" ::: "memory")

// ---------------------------------------------------------------------------
// convert x (fp32) -> hi/lo bf16
// ---------------------------------------------------------------------------
__global__ void convert_x_kernel(const float* __restrict__ X,
                                 __nv_bfloat16* __restrict__ Xh,
                                 __nv_bfloat16* __restrict__ Xl) {
    const int i = (blockIdx.x * blockDim.x + threadIdx.x) * 4;
    const float4 v = *(const float4*)(X + i);
    float a[4] = {v.x, v.y, v.z, v.w};
    uint32_t hp[2], lp[2];
    #pragma unroll
    for (int p = 0; p < 2; p++) {
        __nv_bfloat16 h0 = __float2bfloat16(a[p * 2]);
        __nv_bfloat16 h1 = __float2bfloat16(a[p * 2 + 1]);
        __nv_bfloat16 l0 = __float2bfloat16(a[p * 2]     - __bfloat162float(h0));
        __nv_bfloat16 l1 = __float2bfloat16(a[p * 2 + 1] - __bfloat162float(h1));
        hp[p] = (uint32_t)__bfloat16_as_ushort(h0) | ((uint32_t)__bfloat16_as_ushort(h1) << 16);
        lp[p] = (uint32_t)__bfloat16_as_ushort(l0) | ((uint32_t)__bfloat16_as_ushort(l1) << 16);
    }
    *(uint2*)(Xh + i) = make_uint2(hp[0], hp[1]);
    *(uint2*)(Xl + i) = make_uint2(lp[0], lp[1]);
}

// ---------------------------------------------------------------------------
// convert + transpose W[768 in, 768 out] -> Wt[out, in] hi/lo bf16
// ---------------------------------------------------------------------------
__global__ void convert_wt_kernel(const float* __restrict__ W,
                                  __nv_bfloat16* __restrict__ Wth,
                                  __nv_bfloat16* __restrict__ Wtl) {
    __shared__ float tile[32][33];
    const int bx = blockIdx.x * 32;
    const int by = blockIdx.y * 32;
    const int tx = threadIdx.x, ty = threadIdx.y;
    for (int r = ty; r < 32; r += 8)
        tile[r][tx] = W[(size_t)(by + r) * DD + bx + tx];
    __syncthreads();
    for (int r = ty; r < 32; r += 8) {
        const float v = tile[tx][r];
        const __nv_bfloat16 h = __float2bfloat16(v);
        const __nv_bfloat16 l = __float2bfloat16(v - __bfloat162float(h));
        const size_t o = (size_t)(bx + r) * DD + by + tx;
        Wth[o] = h;
        Wtl[o] = l;
    }
}

// ---------------------------------------------------------------------------
// bf16x3 GEMM via mma.sync: C[M,768] = epi(A @ Wt^T + bias)
//   MODE 0: write fp32 C = acc + bias
//   MODE 1: g = gelu(acc + bias); write bf16 hi/lo (Ch, Cl)
// 128x128 CTA tile, 8 warps (2m x 4n), each warp 64x32. BK=32 double-buffered.
// ---------------------------------------------------------------------------
template<int MODE>
__global__ void __launch_bounds__(256) mma_gemm_kernel(
    const __nv_bfloat16* __restrict__ Ah, const __nv_bfloat16* __restrict__ Al,
    const __nv_bfloat16* __restrict__ Bh, const __nv_bfloat16* __restrict__ Bl,
    const float* __restrict__ bias,
    float* __restrict__ C,
    __nv_bfloat16* __restrict__ Ch, __nv_bfloat16* __restrict__ Cl)
{
    extern __shared__ char sm[];
    const uint32_t smb = s2u(sm);

    const int t    = threadIdx.x;
    const int warp = t >> 5;
    const int lane = t & 31;
    const int wm   = warp >> 2;        // 0..1
    const int wn   = warp & 3;         // 0..3
    const int n0   = blockIdx.x * 128;
    const int m0   = blockIdx.y * 128;

    // ---- cp.async chunk loader ----
    const __nv_bfloat16* srcs[4] = {Ah, Al, Bh, Bl};
    const int row0g[4] = {m0, m0, n0, n0};
    auto prefetch = [&](int c, int s) {
        const int k0 = c * BK;
        const uint32_t sb = smb + s * STAGE_SM;
        #pragma unroll
        for (int i = 0; i < 8; i++) {
            const int idx  = t + 256 * i;         // 0..2047
            const int tile = idx >> 9;            // 512 16B-chunks per tile
            const int rem  = idx & 511;
            const int row  = rem >> 2;
            const int cc   = rem & 3;
            const uint32_t dst = sb + tile * TILE_SM + (row * PADK + cc * 8) * 2;
            cp_async16(dst, srcs[tile] + (size_t)(row0g[tile] + row) * DD + k0 + cc * 8);
        }
        CP_COMMIT();
    };

    // ---- per-lane ldmatrix byte offsets ----
    const int arow   = (lane & 15);
    const int acol8  = (lane >> 4) * 8;
    const int q      = lane >> 3;
    const int brl    = lane & 7;
    const int brow   = (q < 2) ? brl : (8 + brl);
    const int bcol8  = (q & 1) * 8;

    const uint32_t aoff = ((wm * 64 + arow) * PADK + acol8) * 2;   // + mt*16*PADK*2 + k16*2
    const uint32_t boff = ((wn * 32 + brow) * PADK + bcol8) * 2;   // + ntp*16*PADK*2 + k16*2

    float acc[4][4][4];
    #pragma unroll
    for (int i = 0; i < 4; i++)
        #pragma unroll
        for (int j = 0; j < 4; j++)
            #pragma unroll
            for (int r = 0; r < 4; r++) acc[i][j][r] = 0.f;

    prefetch(0, 0);

    for (int c = 0; c < NC; ++c) {
        const int s = c & 1;
        if (c + 1 < NC) { prefetch(c + 1, s ^ 1); CP_WAIT_1(); }
        else            { CP_WAIT_0(); }
        __syncthreads();

        const uint32_t sb  = smb + s * STAGE_SM;
        const uint32_t sAh = sb;
        const uint32_t sAl = sb + TILE_SM;
        const uint32_t sBh = sb + 2 * TILE_SM;
        const uint32_t sBl = sb + 3 * TILE_SM;

        #pragma unroll
        for (int k16 = 0; k16 < BK; k16 += 16) {
            uint32_t ah[4][4], al[4][4], bh[4][2], bl[4][2];
            #pragma unroll
            for (int mt = 0; mt < 4; mt++) {
                const uint32_t ao = aoff + mt * (16 * PADK * 2) + k16 * 2;
                ldsm_x4(ah[mt], sAh + ao);
                ldsm_x4(al[mt], sAl + ao);
            }
            #pragma unroll
            for (int ntp = 0; ntp < 2; ntp++) {
                const uint32_t bo = boff + ntp * (16 * PADK * 2) + k16 * 2;
                uint32_t rh[4], rl[4];
                ldsm_x4(rh, sBh + bo);
                ldsm_x4(rl, sBl + bo);
                bh[ntp * 2][0] = rh[0]; bh[ntp * 2][1] = rh[1];
                bh[ntp * 2 + 1][0] = rh[2]; bh[ntp * 2 + 1][1] = rh[3];
                bl[ntp * 2][0] = rl[0]; bl[ntp * 2][1] = rl[1];
                bl[ntp * 2 + 1][0] = rl[2]; bl[ntp * 2 + 1][1] = rl[3];
            }
            #pragma unroll
            for (int mt = 0; mt < 4; mt++)
                #pragma unroll
                for (int nt = 0; nt < 4; nt++) {
                    mma_bf16(acc[mt][nt], ah[mt], bh[nt]);
                    mma_bf16(acc[mt][nt], ah[mt], bl[nt]);
                    mma_bf16(acc[mt][nt], al[mt], bh[nt]);
                }
        }
        __syncthreads();
    }

    // ---- epilogue: bias (+gelu) + store ----
    const int gid = lane >> 2;
    const int qid = lane & 3;
    float bv[4][2];
    #pragma unroll
    for (int nt = 0; nt < 4; nt++) {
        const int col = n0 + wn * 32 + nt * 8 + qid * 2;
        bv[nt][0] = bias[col];
        bv[nt][1] = bias[col + 1];
    }

    #pragma unroll
    for (int mt = 0; mt < 4; mt++) {
        const int row = m0 + wm * 64 + mt * 16 + gid;
        #pragma unroll
        for (int nt = 0; nt < 4; nt++) {
            const int col = n0 + wn * 32 + nt * 8 + qid * 2;
            float v[4];
            v[0] = acc[mt][nt][0] + bv[nt][0];
            v[1] = acc[mt][nt][1] + bv[nt][1];
            v[2] = acc[mt][nt][2] + bv[nt][0];
            v[3] = acc[mt][nt][3] + bv[nt][1];
            if (MODE == 1) {
                #pragma unroll
                for (int r = 0; r < 4; r++) v[r] = gelu_exact(v[r]);
                #pragma unroll
                for (int half = 0; half < 2; half++) {
                    const size_t off = (size_t)(row + half * 8) * DD + col;
                    __nv_bfloat16 h0 = __float2bfloat16(v[half * 2]);
                    __nv_bfloat16 h1 = __float2bfloat16(v[half * 2 + 1]);
                    __nv_bfloat16 l0 = __float2bfloat16(v[half * 2]     - __bfloat162float(h0));
                    __nv_bfloat16 l1 = __float2bfloat16(v[half * 2 + 1] - __bfloat162float(h1));
                    *(uint32_t*)(Ch + off) =
                        (uint32_t)__bfloat16_as_ushort(h0) | ((uint32_t)__bfloat16_as_ushort(h1) << 16);
                    *(uint32_t*)(Cl + off) =
                        (uint32_t)__bfloat16_as_ushort(l0) | ((uint32_t)__bfloat16_as_ushort(l1) << 16);
                }
            } else {
                *(float2*)(C + (size_t)row * DD + col)       = make_float2(v[0], v[1]);
                *(float2*)(C + (size_t)(row + 8) * DD + col) = make_float2(v[2], v[3]);
            }
        }
    }
}

// ---------------------------------------------------------------------------
// Fused banded attention + LayerNorm (unchanged; proven correct).
// ---------------------------------------------------------------------------
__global__ void __launch_bounds__(256) attn_ln_kernel(
    const float* __restrict__ Q, const float* __restrict__ K,
    const float* __restrict__ V, const float* __restrict__ lnw,
    const float* __restrict__ lnb, float* __restrict__ out)
{
    extern __shared__ float smf[];
    float* Ssh = smf;
    float* Ysh = smf + TQ * JW;
    float* Wk  = Ysh + TQ * DD;
    float* Qs  = Wk;
    float* Ks  = Wk + 16 * TQ;
    float* Vs  = Wk;

    const int t  = threadIdx.x;
    const int bx = blockIdx.x;
    const int b  = bx >> 7;
    const int it = bx & 127;
    const int i0 = it * TQ;
    const long base = (long)b * 4096;
    const int jb = i0 - 256;

    {
        const int tx = t & 31;
        const int ty = t >> 5;
        const int lr = t >> 3;
        const int lc = (t & 7) * 2;

        float acc[4][9];
        #pragma unroll
        for (int i = 0; i < 4; i++)
            #pragma unroll
            for (int j = 0; j < 9; j++) acc[i][j] = 0.f;

        for (int k0 = 0; k0 < DD; k0 += 16) {
            float2 q2 = *(const float2*)&Q[(base + i0 + lr) * DD + k0 + lc];
            Qs[(lc    ) * TQ + lr] = q2.x;
            Qs[(lc + 1) * TQ + lr] = q2.y;
            #pragma unroll
            for (int p = 0; p < 9; p++) {
                const int row = lr + p * 32;
                const int jl  = jb + row;
                float2 kv = make_float2(0.f, 0.f);
                if (jl >= 0)
                    kv = *(const float2*)&K[(base + jl) * DD + k0 + lc];
                Ks[(lc    ) * JW + row] = kv.x;
                Ks[(lc + 1) * JW + row] = kv.y;
            }
            __syncthreads();
            #pragma unroll
            for (int kk = 0; kk < 16; kk++) {
                float qv[4], kv[9];
                #pragma unroll
                for (int i = 0; i < 4; i++) qv[i] = Qs[kk * TQ + ty + 8 * i];
                #pragma unroll
                for (int j = 0; j < 9; j++) kv[j] = Ks[kk * JW + tx + 32 * j];
                #pragma unroll
                for (int i = 0; i < 4; i++)
                    #pragma unroll
                    for (int j = 0; j < 9; j++)
                        acc[i][j] = fmaf(qv[i], kv[j], acc[i][j]);
            }
            __syncthreads();
        }

        #pragma unroll
        for (int i = 0; i < 4; i++) {
            const int ti = ty + 8 * i;
            #pragma unroll
            for (int j = 0; j < 9; j++) {
                const int jw = tx + 32 * j;
                const int jl = jb + jw;
                const bool valid = (jl >= 0) && (jw > ti) && (jw <= ti + 256);
                Ssh[ti * JW + jw] = valid ? acc[i][j] * INV_SCALE : 0.f;
            }
        }
        __syncthreads();
    }

    {
        const int tg = t & 31;
        const int th = t >> 5;
        for (int dc = 0; dc < DD; dc += 128) {
            float acc2[4][4];
            #pragma unroll
            for (int ii = 0; ii < 4; ii++)
                #pragma unroll
                for (int c = 0; c < 4; c++) acc2[ii][c] = 0.f;

            for (int js = 0; js < JW; js += 32) {
                #pragma unroll
                for (int p = 0; p < 4; p++) {
                    const int row = th + p * 8;
                    const int jl  = jb + js + row;
                    float4 vv = make_float4(0.f, 0.f, 0.f, 0.f);
                    if (jl >= 0)
                        vv = *(const float4*)&V[(base + jl) * DD + dc + tg * 4];
                    *(float4*)&Vs[row * 128 + tg * 4] = vv;
                }
                __syncthreads();
                #pragma unroll
                for (int jw = 0; jw < 32; jw++) {
                    const float4 v4 = *(float4*)&Vs[jw * 128 + tg * 4];
                    #pragma unroll
                    for (int ii = 0; ii < 4; ii++) {
                        const float s = Ssh[(th + 8 * ii) * JW + js + jw];
                        acc2[ii][0] = fmaf(s, v4.x, acc2[ii][0]);
                        acc2[ii][1] = fmaf(s, v4.y, acc2[ii][1]);
                        acc2[ii][2] = fmaf(s, v4.z, acc2[ii][2]);
                        acc2[ii][3] = fmaf(s, v4.w, acc2[ii][3]);
                    }
                }
                __syncthreads();
            }
            #pragma unroll
            for (int ii = 0; ii < 4; ii++) {
                const int ti = th + 8 * ii;
                *(float4*)&Ysh[ti * DD + dc + tg * 4] =
                    make_float4(acc2[ii][0], acc2[ii][1], acc2[ii][2], acc2[ii][3]);
            }
        }
        __syncthreads();
    }

    {
        const int warp = t >> 5;
        const int lane = t & 31;
        #pragma unroll
        for (int rr = 0; rr < 4; rr++) {
            const int row = warp * 4 + rr;
            float s = 0.f, ss = 0.f;
            #pragma unroll
            for (int c0 = 0; c0 < DD; c0 += 32) {
                const float y = Ysh[row * DD + c0 + lane];
                s += y; ss += y * y;
            }
            #pragma unroll
            for (int o = 16; o > 0; o >>= 1) {
                s  += __shfl_xor_sync(0xffffffffu, s,  o);
                ss += __shfl_xor_sync(0xffffffffu, ss, o);
            }
            const float mu   = s * (1.f / 768.f);
            const float var  = ss * (1.f / 768.f) - mu * mu;
            const float rstd = rsqrtf(var + 1e-5f);
            #pragma unroll
            for (int c0 = 0; c0 < DD; c0 += 32) {
                const int c = c0 + lane;
                const float y = Ysh[row * DD + c];
                out[(base + i0 + row) * DD + c] = (y - mu) * rstd * lnw[c] + lnb[c];
            }
        }
    }
}

// ---------------------------------------------------------------------------
extern "C" void kernel_launch(void* const* d_in, const int* in_sizes, int n_in,
                              void* d_out, int out_size)
{
    const float* x   = (const float*)d_in[0];
    const float* qw1 = (const float*)d_in[1];
    const float* qb1 = (const float*)d_in[2];
    const float* qw2 = (const float*)d_in[3];
    const float* qb2 = (const float*)d_in[4];
    const float* kw1 = (const float*)d_in[5];
    const float* kb1 = (const float*)d_in[6];
    const float* kw2 = (const float*)d_in[7];
    const float* kb2 = (const float*)d_in[8];
    const float* vw1 = (const float*)d_in[9];
    const float* vb1 = (const float*)d_in[10];
    const float* vw2 = (const float*)d_in[11];
    const float* vb2 = (const float*)d_in[12];
    const float* lnw = (const float*)d_in[13];
    const float* lnb = (const float*)d_in[14];
    float* out = (float*)d_out;

    __nv_bfloat16 *Xh, *Xl, *Hh, *Hl, *Wth, *Wtl;
    float *Q, *K, *V;
    cudaGetSymbolAddress((void**)&Xh, g_Xh);
    cudaGetSymbolAddress((void**)&Xl, g_Xl);
    cudaGetSymbolAddress((void**)&Hh, g_Hh);
    cudaGetSymbolAddress((void**)&Hl, g_Hl);
    cudaGetSymbolAddress((void**)&Wth, g_Wth);
    cudaGetSymbolAddress((void**)&Wtl, g_Wtl);
    cudaGetSymbolAddress((void**)&Q, g_Q);
    cudaGetSymbolAddress((void**)&K, g_K);
    cudaGetSymbolAddress((void**)&V, g_V);

    const int gemm_smem = 2 * STAGE_SM;   // 81920
    cudaFuncSetAttribute(mma_gemm_kernel<0>,
                         cudaFuncAttributeMaxDynamicSharedMemorySize, gemm_smem);
    cudaFuncSetAttribute(mma_gemm_kernel<1>,
                         cudaFuncAttributeMaxDynamicSharedMemorySize, gemm_smem);

    convert_x_kernel<<<(MT * DD) / (256 * 4), 256>>>(x, Xh, Xl);

    const dim3 gw(24, 24);
    const dim3 bw(32, 8);
    const dim3 gg(DD / 128, MT / 128);   // (6, 128)

    const float* W1[3] = {qw1, kw1, vw1};
    const float* B1[3] = {qb1, kb1, vb1};
    const float* W2[3] = {qw2, kw2, vw2};
    const float* B2[3] = {qb2, kb2, vb2};
    float* OUTP[3] = {Q, K, V};

    for (int m = 0; m < 3; m++) {
        convert_wt_kernel<<<gw, bw>>>(W1[m], Wth, Wtl);
        mma_gemm_kernel<1><<<gg, 256, gemm_smem>>>(Xh, Xl, Wth, Wtl, B1[m],
                                                   nullptr, Hh, Hl);
        convert_wt_kernel<<<gw, bw>>>(W2[m], Wth, Wtl);
        mma_gemm_kernel<0><<<gg, 256, gemm_smem>>>(Hh, Hl, Wth, Wtl, B2[m],
                                                   OUTP[m], nullptr, nullptr);
    }

    const int attn_smem = (TQ * JW + TQ * DD + 5120) * 4;
    cudaFuncSetAttribute(attn_ln_kernel,
                         cudaFuncAttributeMaxDynamicSharedMemorySize, attn_smem);
    attn_ln_kernel<<<MT / TQ, 256, attn_smem>>>(Q, K, V, lnw, lnb, out);
}

// round 4
// speedup vs baseline: 2.6286x; 1.3444x over previous
#include <cuda_runtime.h>
#include <cuda_bf16.h>
#include <math.h>
#include <stdint.h>

#define MT 16384   // B*T rows
#define DD 768     // embed dim

// ---- GEMM tiling ----
#define BK 32
#define NC (DD / BK)       // 24
#define PADK 40
#define TILE_SM (128 * PADK * 2)
#define STAGE_SM (4 * TILE_SM)

// ---- attention tiling ----
#define TQ 32
#define JW 288
#define SSTR 296           // padded S row (bf16 elems)
#define VSTR 264           // padded V row (bf16 elems)
// smem layout (bytes)
#define S_H_OFF 0
#define S_L_OFF 18944
#define A_OFF   37888
#define P1_STAGE 51200
#define P1_KH 0
#define P1_KL 23040
#define P1_QH 46080
#define P1_QL 48640
#define P2_STAGE 33792
#define P2_VH 0
#define P2_VL 16896
#define Y_OFF  105472      // A_OFF + 2*P2_STAGE
#define ATTN_SMEM 203776   // Y_OFF + 32*768*4

// 1/sqrt(768*256)
#define INV_SCALE 0.0022552744890219756f

// ---------------------------------------------------------------------------
// scratch
// ---------------------------------------------------------------------------
__device__ __nv_bfloat16 g_Xh[MT * DD];
__device__ __nv_bfloat16 g_Xl[MT * DD];
__device__ __nv_bfloat16 g_Hh[MT * DD];
__device__ __nv_bfloat16 g_Hl[MT * DD];
__device__ __nv_bfloat16 g_Wth[DD * DD];
__device__ __nv_bfloat16 g_Wtl[DD * DD];
__device__ __nv_bfloat16 g_Qh[MT * DD];
__device__ __nv_bfloat16 g_Ql[MT * DD];
__device__ __nv_bfloat16 g_Kh[MT * DD];
__device__ __nv_bfloat16 g_Kl[MT * DD];
__device__ __nv_bfloat16 g_Vh[MT * DD];
__device__ __nv_bfloat16 g_Vl[MT * DD];

__device__ __forceinline__ float gelu_exact(float x) {
    return 0.5f * x * (1.0f + erff(x * 0.70710678118654752f));
}

__device__ __forceinline__ uint32_t s2u(const void* p) {
    uint32_t a;
    asm("{ .reg .u64 t; cvta.to.shared.u64 t, %1; cvt.u32.u64 %0, t; }"
        : "=r"(a) : "l"(p));
    return a;
}

// ---- tensor-core primitives (compute_80 features) ----
__device__ __forceinline__ void mma_bf16(float* c, const uint32_t* a, const uint32_t* b) {
    asm volatile(
        "mma.sync.aligned.m16n8k16.row.col.f32.bf16.bf16.f32 "
        "{%0,%1,%2,%3}, {%4,%5,%6,%7}, {%8,%9}, {%0,%1,%2,%3};"
        : "+f"(c[0]), "+f"(c[1]), "+f"(c[2]), "+f"(c[3])
        : "r"(a[0]), "r"(a[1]), "r"(a[2]), "r"(a[3]), "r"(b[0]), "r"(b[1]));
}
__device__ __forceinline__ void ldsm_x4(uint32_t* r, uint32_t addr) {
    asm volatile("ldmatrix.sync.aligned.m8n8.x4.shared.b16 {%0,%1,%2,%3}, [%4];"
                 : "=r"(r[0]), "=r"(r[1]), "=r"(r[2]), "=r"(r[3]) : "r"(addr));
}
__device__ __forceinline__ void ldsm_x4_t(uint32_t* r, uint32_t addr) {
    asm volatile("ldmatrix.sync.aligned.m8n8.x4.trans.shared.b16 {%0,%1,%2,%3}, [%4];"
                 : "=r"(r[0]), "=r"(r[1]), "=r"(r[2]), "=r"(r[3]) : "r"(addr));
}
__device__ __forceinline__ void ldsm_x2(uint32_t* r, uint32_t addr) {
    asm volatile("ldmatrix.sync.aligned.m8n8.x2.shared.b16 {%0,%1}, [%2];"
                 : "=r"(r[0]), "=r"(r[1]) : "r"(addr));
}
__device__ __forceinline__ void cp_async16(uint32_t dst, const void* src) {
    asm volatile("cp.async.cg.shared.global [%0], [%1], 16;" :: "r"(dst), "l"(src));
}
__device__ __forceinline__ void cp_async16z(uint32_t dst, const void* src, int sz) {
    asm volatile("cp.async.cg.shared.global [%0], [%1], 16, %2;"
                 :: "r"(dst), "l"(src), "r"(sz));
}
#define CP_COMMIT()  asm volatile("cp.async.commit_group;" ::: "memory")
#define CP_WAIT_1()  asm volatile("cp.async.wait_group 1;" ::: "memory")
#define CP_WAIT_0()  asm volatile("cp.async.wait_group 0;" ::: "memory")

__device__ __forceinline__ uint32_t pack_hl(float v, float w, uint32_t& lo) {
    __nv_bfloat16 h0 = __float2bfloat16(v);
    __nv_bfloat16 h1 = __float2bfloat16(w);
    __nv_bfloat16 l0 = __float2bfloat16(v - __bfloat162float(h0));
    __nv_bfloat16 l1 = __float2bfloat16(w - __bfloat162float(h1));
    lo = (uint32_t)__bfloat16_as_ushort(l0) | ((uint32_t)__bfloat16_as_ushort(l1) << 16);
    return (uint32_t)__bfloat16_as_ushort(h0) | ((uint32_t)__bfloat16_as_ushort(h1) << 16);
}

// ---------------------------------------------------------------------------
// convert x (fp32) -> hi/lo bf16
// ---------------------------------------------------------------------------
__global__ void convert_x_kernel(const float* __restrict__ X,
                                 __nv_bfloat16* __restrict__ Xh,
                                 __nv_bfloat16* __restrict__ Xl) {
    const int i = (blockIdx.x * blockDim.x + threadIdx.x) * 4;
    const float4 v = *(const float4*)(X + i);
    uint32_t h0, h1, l0, l1;
    h0 = pack_hl(v.x, v.y, l0);
    h1 = pack_hl(v.z, v.w, l1);
    *(uint2*)(Xh + i) = make_uint2(h0, h1);
    *(uint2*)(Xl + i) = make_uint2(l0, l1);
}

// ---------------------------------------------------------------------------
// convert + transpose W[768 in, 768 out] -> Wt[out, in] hi/lo bf16
// ---------------------------------------------------------------------------
__global__ void convert_wt_kernel(const float* __restrict__ W,
                                  __nv_bfloat16* __restrict__ Wth,
                                  __nv_bfloat16* __restrict__ Wtl) {
    __shared__ float tile[32][33];
    const int bx = blockIdx.x * 32;
    const int by = blockIdx.y * 32;
    const int tx = threadIdx.x, ty = threadIdx.y;
    for (int r = ty; r < 32; r += 8)
        tile[r][tx] = W[(size_t)(by + r) * DD + bx + tx];
    __syncthreads();
    for (int r = ty; r < 32; r += 8) {
        const float v = tile[tx][r];
        const __nv_bfloat16 h = __float2bfloat16(v);
        const __nv_bfloat16 l = __float2bfloat16(v - __bfloat162float(h));
        const size_t o = (size_t)(bx + r) * DD + by + tx;
        Wth[o] = h;
        Wtl[o] = l;
    }
}

// ---------------------------------------------------------------------------
// bf16x3 GEMM via mma.sync; output always bf16 hi/lo (+bias, optional GELU)
// ---------------------------------------------------------------------------
template<int GELU>
__global__ void __launch_bounds__(256) mma_gemm_kernel(
    const __nv_bfloat16* __restrict__ Ah, const __nv_bfloat16* __restrict__ Al,
    const __nv_bfloat16* __restrict__ Bh, const __nv_bfloat16* __restrict__ Bl,
    const float* __restrict__ bias,
    __nv_bfloat16* __restrict__ Ch, __nv_bfloat16* __restrict__ Cl)
{
    extern __shared__ char sm[];
    const uint32_t smb = s2u(sm);

    const int t    = threadIdx.x;
    const int warp = t >> 5;
    const int lane = t & 31;
    const int wm   = warp >> 2;
    const int wn   = warp & 3;
    const int n0   = blockIdx.x * 128;
    const int m0   = blockIdx.y * 128;

    const __nv_bfloat16* srcs[4] = {Ah, Al, Bh, Bl};
    const int row0g[4] = {m0, m0, n0, n0};
    auto prefetch = [&](int c, int s) {
        const int k0 = c * BK;
        const uint32_t sb = smb + s * STAGE_SM;
        #pragma unroll
        for (int i = 0; i < 8; i++) {
            const int idx  = t + 256 * i;
            const int tile = idx >> 9;
            const int rem  = idx & 511;
            const int row  = rem >> 2;
            const int cc   = rem & 3;
            const uint32_t dst = sb + tile * TILE_SM + (row * PADK + cc * 8) * 2;
            cp_async16(dst, srcs[tile] + (size_t)(row0g[tile] + row) * DD + k0 + cc * 8);
        }
        CP_COMMIT();
    };

    const int arow   = (lane & 15);
    const int acol8  = (lane >> 4) * 8;
    const int q      = lane >> 3;
    const int brl    = lane & 7;
    const int brow   = (q < 2) ? brl : (8 + brl);
    const int bcol8  = (q & 1) * 8;

    const uint32_t aoff = ((wm * 64 + arow) * PADK + acol8) * 2;
    const uint32_t boff = ((wn * 32 + brow) * PADK + bcol8) * 2;

    float acc[4][4][4];
    #pragma unroll
    for (int i = 0; i < 4; i++)
        #pragma unroll
        for (int j = 0; j < 4; j++)
            #pragma unroll
            for (int r = 0; r < 4; r++) acc[i][j][r] = 0.f;

    prefetch(0, 0);

    for (int c = 0; c < NC; ++c) {
        const int s = c & 1;
        if (c + 1 < NC) { prefetch(c + 1, s ^ 1); CP_WAIT_1(); }
        else            { CP_WAIT_0(); }
        __syncthreads();

        const uint32_t sb  = smb + s * STAGE_SM;
        const uint32_t sAh = sb;
        const uint32_t sAl = sb + TILE_SM;
        const uint32_t sBh = sb + 2 * TILE_SM;
        const uint32_t sBl = sb + 3 * TILE_SM;

        #pragma unroll
        for (int k16 = 0; k16 < BK; k16 += 16) {
            uint32_t ah[4][4], al[4][4], bh[4][2], bl[4][2];
            #pragma unroll
            for (int mt = 0; mt < 4; mt++) {
                const uint32_t ao = aoff + mt * (16 * PADK * 2) + k16 * 2;
                ldsm_x4(ah[mt], sAh + ao);
                ldsm_x4(al[mt], sAl + ao);
            }
            #pragma unroll
            for (int ntp = 0; ntp < 2; ntp++) {
                const uint32_t bo = boff + ntp * (16 * PADK * 2) + k16 * 2;
                uint32_t rh[4], rl[4];
                ldsm_x4(rh, sBh + bo);
                ldsm_x4(rl, sBl + bo);
                bh[ntp * 2][0] = rh[0]; bh[ntp * 2][1] = rh[1];
                bh[ntp * 2 + 1][0] = rh[2]; bh[ntp * 2 + 1][1] = rh[3];
                bl[ntp * 2][0] = rl[0]; bl[ntp * 2][1] = rl[1];
                bl[ntp * 2 + 1][0] = rl[2]; bl[ntp * 2 + 1][1] = rl[3];
            }
            #pragma unroll
            for (int mt = 0; mt < 4; mt++)
                #pragma unroll
                for (int nt = 0; nt < 4; nt++) {
                    mma_bf16(acc[mt][nt], ah[mt], bh[nt]);
                    mma_bf16(acc[mt][nt], ah[mt], bl[nt]);
                    mma_bf16(acc[mt][nt], al[mt], bh[nt]);
                }
        }
        __syncthreads();
    }

    const int gid = lane >> 2;
    const int qid = lane & 3;
    float bv[4][2];
    #pragma unroll
    for (int nt = 0; nt < 4; nt++) {
        const int col = n0 + wn * 32 + nt * 8 + qid * 2;
        bv[nt][0] = bias[col];
        bv[nt][1] = bias[col + 1];
    }

    #pragma unroll
    for (int mt = 0; mt < 4; mt++) {
        const int row = m0 + wm * 64 + mt * 16 + gid;
        #pragma unroll
        for (int nt = 0; nt < 4; nt++) {
            const int col = n0 + wn * 32 + nt * 8 + qid * 2;
            #pragma unroll
            for (int half = 0; half < 2; half++) {
                float v0 = acc[mt][nt][half * 2]     + bv[nt][0];
                float v1 = acc[mt][nt][half * 2 + 1] + bv[nt][1];
                if (GELU) { v0 = gelu_exact(v0); v1 = gelu_exact(v1); }
                uint32_t lo;
                const uint32_t hi = pack_hl(v0, v1, lo);
                const size_t off = (size_t)(row + half * 8) * DD + col;
                *(uint32_t*)(Ch + off) = hi;
                *(uint32_t*)(Cl + off) = lo;
            }
        }
    }
}

// ---------------------------------------------------------------------------
// Fused banded attention + LayerNorm via mma.sync bf16x3.
// Block = (batch, 32-query tile). 256 threads, 8 warps (2m x 4n).
// ---------------------------------------------------------------------------
__global__ void __launch_bounds__(256) attn_ln_kernel(
    const __nv_bfloat16* __restrict__ Qh, const __nv_bfloat16* __restrict__ Ql,
    const __nv_bfloat16* __restrict__ Kh, const __nv_bfloat16* __restrict__ Kl,
    const __nv_bfloat16* __restrict__ Vh, const __nv_bfloat16* __restrict__ Vl,
    const float* __restrict__ lnw, const float* __restrict__ lnb,
    float* __restrict__ out)
{
    extern __shared__ char smc[];
    const uint32_t smb = s2u(smc);
    const uint32_t smSh = smb + S_H_OFF;
    const uint32_t smSl = smb + S_L_OFF;
    const uint32_t smA  = smb + A_OFF;
    float* Ysh = (float*)(smc + Y_OFF);

    const int t    = threadIdx.x;
    const int warp = t >> 5;
    const int lane = t & 31;
    const int wm   = warp >> 2;        // 0..1
    const int wn   = warp & 3;         // 0..3
    const int gid  = lane >> 2;
    const int qid  = lane & 3;

    const int bx = blockIdx.x;
    const int b  = bx >> 7;
    const int i0 = (bx & 127) * TQ;    // batch-local first query
    const long base = (long)b * 4096;
    const int jb = i0 - 256;           // window start (batch-local)

    // ---- ldmatrix lane addressing pieces ----
    const int l15   = lane & 15;
    const int hi8   = (lane >> 4) * 8;
    const int q3    = lane >> 3;
    const int brl   = lane & 7;
    const int brow  = (q3 < 2) ? brl : (8 + brl);
    const int bcol8 = (q3 & 1) * 8;

    // =================== phase 1: S = mask(Q @ K^T) ===================
    auto p1_prefetch = [&](int c, int s) {
        const int k0 = c * 32;
        const uint32_t sb = smA + s * P1_STAGE;
        #pragma unroll
        for (int i = 0; i < 10; i++) {
            const int idx = t + 256 * i;
            if (idx < 2304) {
                const int hl = idx >= 1152;
                const int r  = (idx - hl * 1152) >> 2;
                const int cc = idx & 3;
                const uint32_t dst = sb + (hl ? P1_KL : P1_KH) + r * (PADK * 2) + cc * 16;
                const int jl = jb + r;
                const int jlc = jl < 0 ? 0 : jl;
                const __nv_bfloat16* src =
                    (hl ? Kl : Kh) + (size_t)(base + jlc) * DD + k0 + cc * 8;
                cp_async16z(dst, src, jl < 0 ? 0 : 16);
            } else {
                const int idq = idx - 2304;
                const int hl = idq >= 128;
                const int r  = (idq - hl * 128) >> 2;
                const int cc = idq & 3;
                const uint32_t dst = sb + (hl ? P1_QL : P1_QH) + r * (PADK * 2) + cc * 16;
                const __nv_bfloat16* src =
                    (hl ? Ql : Qh) + (size_t)(base + i0 + r) * DD + k0 + cc * 8;
                cp_async16(dst, src);
            }
        }
        CP_COMMIT();
    };

    float acc[9][4];
    #pragma unroll
    for (int n = 0; n < 9; n++)
        #pragma unroll
        for (int r = 0; r < 4; r++) acc[n][r] = 0.f;

    p1_prefetch(0, 0);

    for (int c = 0; c < 24; ++c) {
        const int s = c & 1;
        if (c + 1 < 24) { p1_prefetch(c + 1, s ^ 1); CP_WAIT_1(); }
        else            { CP_WAIT_0(); }
        __syncthreads();

        const uint32_t sb = smA + s * P1_STAGE;
        #pragma unroll
        for (int k16 = 0; k16 < 32; k16 += 16) {
            uint32_t ah[4], al[4];
            const uint32_t ao = ((wm * 16 + l15) * PADK + k16 + hi8) * 2;
            ldsm_x4(ah, sb + P1_QH + ao);
            ldsm_x4(al, sb + P1_QL + ao);

            uint32_t bh[9][2], bl[9][2];
            #pragma unroll
            for (int p = 0; p < 4; p++) {
                const int n0 = wn * 72 + p * 16;
                const uint32_t bo = ((n0 + brow) * PADK + k16 + bcol8) * 2;
                uint32_t r4[4];
                ldsm_x4(r4, sb + P1_KH + bo);
                bh[2*p][0] = r4[0]; bh[2*p][1] = r4[1];
                bh[2*p+1][0] = r4[2]; bh[2*p+1][1] = r4[3];
                ldsm_x4(r4, sb + P1_KL + bo);
                bl[2*p][0] = r4[0]; bl[2*p][1] = r4[1];
                bl[2*p+1][0] = r4[2]; bl[2*p+1][1] = r4[3];
            }
            {
                const int n0 = wn * 72 + 64;
                const uint32_t bo2 = ((n0 + brl) * PADK + k16 + ((lane & 8) ? 8 : 0)) * 2;
                ldsm_x2(bh[8], sb + P1_KH + bo2);
                ldsm_x2(bl[8], sb + P1_KL + bo2);
            }
            #pragma unroll
            for (int nt = 0; nt < 9; nt++) {
                mma_bf16(acc[nt], ah, bh[nt]);
                mma_bf16(acc[nt], ah, bl[nt]);
                mma_bf16(acc[nt], al, bh[nt]);
            }
        }
        __syncthreads();
    }

    // mask + scale + split hi/lo into S smem
    #pragma unroll
    for (int nt = 0; nt < 9; nt++) {
        const int jw0 = wn * 72 + nt * 8 + qid * 2;
        #pragma unroll
        for (int half = 0; half < 2; half++) {
            const int ti = wm * 16 + gid + half * 8;
            float v0 = acc[nt][half * 2];
            float v1 = acc[nt][half * 2 + 1];
            const bool ok0 = (jb + jw0     >= 0) && (jw0     > ti) && (jw0     <= ti + 256);
            const bool ok1 = (jb + jw0 + 1 >= 0) && (jw0 + 1 > ti) && (jw0 + 1 <= ti + 256);
            v0 = ok0 ? v0 * INV_SCALE : 0.f;
            v1 = ok1 ? v1 * INV_SCALE : 0.f;
            uint32_t lo;
            const uint32_t hi = pack_hl(v0, v1, lo);
            const uint32_t so = (ti * SSTR + jw0) * 2;
            *(uint32_t*)(smc + S_H_OFF + so) = hi;
            *(uint32_t*)(smc + S_L_OFF + so) = lo;
        }
    }
    __syncthreads();

    // =================== phase 2: Y = S @ V ===================
    auto p2_prefetch = [&](int iter, int s) {
        const int dc = (iter / 9) * 256;
        const int js = (iter % 9) * 32;
        const uint32_t sb = smA + s * P2_STAGE;
        #pragma unroll
        for (int i = 0; i < 8; i++) {
            const int idx = t + 256 * i;
            const int hl  = idx >= 1024;
            const int idv = idx - hl * 1024;
            const int r   = idv >> 5;
            const int cc  = idv & 31;
            const uint32_t dst = sb + (hl ? P2_VL : P2_VH) + r * (VSTR * 2) + cc * 16;
            const int jl  = jb + js + r;
            const int jlc = jl < 0 ? 0 : jl;
            const __nv_bfloat16* src =
                (hl ? Vl : Vh) + (size_t)(base + jlc) * DD + dc + cc * 8;
            cp_async16z(dst, src, jl < 0 ? 0 : 16);
        }
        CP_COMMIT();
    };

    float acc2[8][4];
    #pragma unroll
    for (int n = 0; n < 8; n++)
        #pragma unroll
        for (int r = 0; r < 4; r++) acc2[n][r] = 0.f;

    p2_prefetch(0, 0);

    for (int iter = 0; iter < 27; ++iter) {
        const int s = iter & 1;
        if (iter + 1 < 27) { p2_prefetch(iter + 1, s ^ 1); CP_WAIT_1(); }
        else               { CP_WAIT_0(); }
        __syncthreads();

        const int js = (iter % 9) * 32;
        const uint32_t sb = smA + s * P2_STAGE;
        #pragma unroll
        for (int k16 = 0; k16 < 32; k16 += 16) {
            uint32_t ah[4], al[4];
            const uint32_t ao = ((wm * 16 + l15) * SSTR + js + k16 + hi8) * 2;
            ldsm_x4(ah, smSh + ao);
            ldsm_x4(al, smSl + ao);

            uint32_t bh[8][2], bl[8][2];
            #pragma unroll
            for (int p = 0; p < 4; p++) {
                const int n0 = wn * 64 + p * 16;
                const uint32_t bo = ((k16 + l15) * VSTR + n0 + hi8) * 2;
                uint32_t r4[4];
                ldsm_x4_t(r4, sb + P2_VH + bo);
                bh[2*p][0] = r4[0]; bh[2*p][1] = r4[1];
                bh[2*p+1][0] = r4[2]; bh[2*p+1][1] = r4[3];
                ldsm_x4_t(r4, sb + P2_VL + bo);
                bl[2*p][0] = r4[0]; bl[2*p][1] = r4[1];
                bl[2*p+1][0] = r4[2]; bl[2*p+1][1] = r4[3];
            }
            #pragma unroll
            for (int nt = 0; nt < 8; nt++) {
                mma_bf16(acc2[nt], ah, bh[nt]);
                mma_bf16(acc2[nt], ah, bl[nt]);
                mma_bf16(acc2[nt], al, bh[nt]);
            }
        }

        if ((iter % 9) == 8) {
            const int dc = (iter / 9) * 256;
            #pragma unroll
            for (int nt = 0; nt < 8; nt++) {
                const int col = dc + wn * 64 + nt * 8 + qid * 2;
                #pragma unroll
                for (int half = 0; half < 2; half++) {
                    const int row = wm * 16 + gid + half * 8;
                    *(float2*)&Ysh[row * DD + col] =
                        make_float2(acc2[nt][half * 2], acc2[nt][half * 2 + 1]);
                }
            }
            #pragma unroll
            for (int n = 0; n < 8; n++)
                #pragma unroll
                for (int r = 0; r < 4; r++) acc2[n][r] = 0.f;
        }
        __syncthreads();
    }

    // =================== phase 3: LayerNorm ===================
    {
        #pragma unroll
        for (int rr = 0; rr < 4; rr++) {
            const int row = warp * 4 + rr;
            float s = 0.f, ss = 0.f;
            #pragma unroll
            for (int c0 = 0; c0 < DD; c0 += 32) {
                const float y = Ysh[row * DD + c0 + lane];
                s += y; ss += y * y;
            }
            #pragma unroll
            for (int o = 16; o > 0; o >>= 1) {
                s  += __shfl_xor_sync(0xffffffffu, s,  o);
                ss += __shfl_xor_sync(0xffffffffu, ss, o);
            }
            const float mu   = s * (1.f / 768.f);
            const float var  = ss * (1.f / 768.f) - mu * mu;
            const float rstd = rsqrtf(var + 1e-5f);
            #pragma unroll
            for (int c0 = 0; c0 < DD; c0 += 32) {
                const int c = c0 + lane;
                const float y = Ysh[row * DD + c];
                out[(base + i0 + row) * DD + c] = (y - mu) * rstd * lnw[c] + lnb[c];
            }
        }
    }
}

// ---------------------------------------------------------------------------
extern "C" void kernel_launch(void* const* d_in, const int* in_sizes, int n_in,
                              void* d_out, int out_size)
{
    const float* x   = (const float*)d_in[0];
    const float* qw1 = (const float*)d_in[1];
    const float* qb1 = (const float*)d_in[2];
    const float* qw2 = (const float*)d_in[3];
    const float* qb2 = (const float*)d_in[4];
    const float* kw1 = (const float*)d_in[5];
    const float* kb1 = (const float*)d_in[6];
    const float* kw2 = (const float*)d_in[7];
    const float* kb2 = (const float*)d_in[8];
    const float* vw1 = (const float*)d_in[9];
    const float* vb1 = (const float*)d_in[10];
    const float* vw2 = (const float*)d_in[11];
    const float* vb2 = (const float*)d_in[12];
    const float* lnw = (const float*)d_in[13];
    const float* lnb = (const float*)d_in[14];
    float* out = (float*)d_out;

    __nv_bfloat16 *Xh, *Xl, *Hh, *Hl, *Wth, *Wtl, *Qh, *Ql, *Kh, *Kl, *Vh, *Vl;
    cudaGetSymbolAddress((void**)&Xh, g_Xh);
    cudaGetSymbolAddress((void**)&Xl, g_Xl);
    cudaGetSymbolAddress((void**)&Hh, g_Hh);
    cudaGetSymbolAddress((void**)&Hl, g_Hl);
    cudaGetSymbolAddress((void**)&Wth, g_Wth);
    cudaGetSymbolAddress((void**)&Wtl, g_Wtl);
    cudaGetSymbolAddress((void**)&Qh, g_Qh);
    cudaGetSymbolAddress((void**)&Ql, g_Ql);
    cudaGetSymbolAddress((void**)&Kh, g_Kh);
    cudaGetSymbolAddress((void**)&Kl, g_Kl);
    cudaGetSymbolAddress((void**)&Vh, g_Vh);
    cudaGetSymbolAddress((void**)&Vl, g_Vl);

    const int gemm_smem = 2 * STAGE_SM;   // 81920
    cudaFuncSetAttribute(mma_gemm_kernel<0>,
                         cudaFuncAttributeMaxDynamicSharedMemorySize, gemm_smem);
    cudaFuncSetAttribute(mma_gemm_kernel<1>,
                         cudaFuncAttributeMaxDynamicSharedMemorySize, gemm_smem);
    cudaFuncSetAttribute(attn_ln_kernel,
                         cudaFuncAttributeMaxDynamicSharedMemorySize, ATTN_SMEM);

    convert_x_kernel<<<(MT * DD) / (256 * 4), 256>>>(x, Xh, Xl);

    const dim3 gw(24, 24);
    const dim3 bw(32, 8);
    const dim3 gg(DD / 128, MT / 128);

    const float* W1[3] = {qw1, kw1, vw1};
    const float* B1[3] = {qb1, kb1, vb1};
    const float* W2[3] = {qw2, kw2, vw2};
    const float* B2[3] = {qb2, kb2, vb2};
    __nv_bfloat16* OH[3] = {Qh, Kh, Vh};
    __nv_bfloat16* OL[3] = {Ql, Kl, Vl};

    for (int m = 0; m < 3; m++) {
        convert_wt_kernel<<<gw, bw>>>(W1[m], Wth, Wtl);
        mma_gemm_kernel<1><<<gg, 256, gemm_smem>>>(Xh, Xl, Wth, Wtl, B1[m], Hh, Hl);
        convert_wt_kernel<<<gw, bw>>>(W2[m], Wth, Wtl);
        mma_gemm_kernel<0><<<gg, 256, gemm_smem>>>(Hh, Hl, Wth, Wtl, B2[m], OH[m], OL[m]);
    }

    attn_ln_kernel<<<MT / TQ, 256, ATTN_SMEM>>>(Qh, Ql, Kh, Kl, Vh, Vl, lnw, lnb, out);
}